// round 6
// baseline (speedup 1.0000x reference)
#include <cuda_runtime.h>
#include <cstdint>
#include <cfloat>

typedef unsigned long long ull;
typedef unsigned int u32;

#define N_ROWS  32768
#define C_DIM   256
#define K_CODES 1024
#define NCB     8          // code-blocks of 128
#define NCHUNK  16         // logical K chunks of 32 (512 total: hi*hi + hi*lo)
#define GAP_TH  0.25f      // ~19 sigma of dropped-term error (rms ~1e-2)
#define NSTAGE  3
#define STAGE_BYTES 32768
#define SMEM_MMA (NSTAGE * STAGE_BYTES)   // 98304

// fragment-native global layouts
// zfr: [row_tile(2048)][kt(32) hi only][lane 32][reg 4]
// efr: [code_tile(128)][klog(64: hi,lo)][lane 32][reg 2]
__device__ float zfr[(size_t)(N_ROWS / 16) * 32 * 128];
__device__ float efr[(size_t)(K_CODES / 8) * 64 * 64];
__device__ float g_enorm[K_CODES];
__device__ int   g_idx[N_ROWS];
__device__ float g_pd[NCB * N_ROWS];
__device__ float g_ps[NCB * N_ROWS];
__device__ int   g_pi[NCB * N_ROWS];
__device__ int   g_nflag;
__device__ int   g_flagrows[N_ROWS];
__device__ float g_partial[256];

// ---------------- helpers ----------------
__device__ __forceinline__ u32 smem_u32(const void* p) {
    return (u32)__cvta_generic_to_shared(p);
}
__device__ __forceinline__ void cp16(u32 dst, const void* src) {
    asm volatile("cp.async.cg.shared.global [%0], [%1], 16;" :: "r"(dst), "l"(src));
}
__device__ __forceinline__ float tf32_rna(float v) {
    u32 r; asm("cvt.rna.satfinite.tf32.f32 %0, %1;" : "=r"(r) : "f"(v));
    return __uint_as_float(r);
}
__device__ __forceinline__ void mma8(float* d, uint4 a, uint2 b) {
    asm("mma.sync.aligned.m16n8k8.row.col.f32.tf32.tf32.f32 "
        "{%0,%1,%2,%3}, {%4,%5,%6,%7}, {%8,%9}, {%0,%1,%2,%3};"
        : "+f"(d[0]), "+f"(d[1]), "+f"(d[2]), "+f"(d[3])
        : "r"(a.x), "r"(a.y), "r"(a.z), "r"(a.w), "r"(b.x), "r"(b.y));
}
__device__ __forceinline__ void upd(float& b1, float& b2, int& i1, float v, int k) {
    if (v < b1 || (v == b1 && k < i1)) { b2 = b1; b1 = v; i1 = k; }
    else if (v < b2) b2 = v;
}

// ---------------------------------------------------------------------------
// prep: z -> fragment layout (hi only)
// A-frag map: lane=(r%8)*4+(k%4), reg=((r%16)/8)+2*((k%8)/4)
// ---------------------------------------------------------------------------
__global__ void k_prep_z(const float* __restrict__ z_e) {
    __shared__ float t[32 * 260];
    int tid = threadIdx.x;
    int r0 = blockIdx.x * 32;
    int b = r0 >> 10, hw0 = r0 & 1023;
    if (blockIdx.x == 0 && tid == 0) g_nflag = 0;
    for (int i = tid; i < 32 * 256; i += 256) {
        int c = i >> 5, r = i & 31;
        t[r * 260 + c] = z_e[(((size_t)(b * C_DIM + c)) << 10) + hw0 + r];
    }
    __syncthreads();
    int rt0 = r0 >> 4;
    for (int i = tid; i < 32 * 256; i += 256) {
        int within = i & 127;
        int tile = i >> 7;               // 0..63
        int rtl = tile >> 5;             // 0..1
        int kt  = tile & 31;             // 0..31
        int lane = within >> 2, reg = within & 3;
        int rl = rtl * 16 + (lane >> 2) + ((reg & 1) << 3);
        int cmod = (kt << 3) + (lane & 3) + ((reg >> 1) << 2);
        float v = t[rl * 260 + cmod];
        zfr[(((size_t)(rt0 + rtl) * 32 + kt) << 7) + within] = tf32_rna(v);
    }
}

// ---------------------------------------------------------------------------
// prep: e -> fragment layout, sections [hi, lo] of (-2*emb)
// B-frag map: lane=(n%8)*4+(k%4), reg=(k%8)/4
// ---------------------------------------------------------------------------
__global__ void k_prep_e(const float* __restrict__ emb) {
    size_t base = (size_t)blockIdx.x * 4096;
    for (int j = threadIdx.x; j < 4096; j += 256) {
        size_t idx = base + j;
        int within = (int)(idx & 63);
        int tile = (int)(idx >> 6);
        int nt = tile >> 6, kt = tile & 63;
        int lane = within >> 1, reg = within & 1;
        int code = nt * 8 + (lane >> 2);
        int sec = kt >> 5;
        int cmod = ((kt & 31) << 3) + (lane & 3) + (reg << 2);
        float v = -2.0f * emb[code * 256 + cmod];
        float hi = tf32_rna(v);
        efr[idx] = sec ? tf32_rna(v - hi) : hi;
    }
}

__global__ void k_enorm(const float* __restrict__ emb) {
    int code = blockIdx.x * 8 + (threadIdx.x >> 5);
    int lane = threadIdx.x & 31;
    const float4* p = (const float4*)(emb + code * C_DIM);
    float4 a = p[lane];
    float4 b = p[lane + 32];
    float s = a.x*a.x + a.y*a.y + a.z*a.z + a.w*a.w
            + b.x*b.x + b.y*b.y + b.z*b.z + b.w*b.w;
    #pragma unroll
    for (int m = 16; m; m >>= 1) s += __shfl_xor_sync(0xffffffffu, s, m);
    if (lane == 0) g_enorm[code] = s;
}

// ---------------------------------------------------------------------------
// main: tf32 mma.sync GEMM (2-term split) + argmin (best + second-best)
// CTA 128 rows x 128 codes, 8 warps (4 row x 2 col), warp tile 32x64.
// 3-stage cp.async ring, 2 CTAs/SM.
// ---------------------------------------------------------------------------
__device__ __forceinline__ void load_chunk(u32 base, int buf, int ch,
                                           int rt0, int cb, int tid)
{
    u32 dst = base + (u32)buf * STAGE_BYTES;
    #pragma unroll
    for (int t2 = 0; t2 < 4; t2++) {
        int t = tid + t2 * 256;
        int tile = t >> 5, part = t & 31;
        int kt = tile >> 3, mt = tile & 7;
        int kp = (ch * 4 + kt) & 31;             // hi section repeats for lo pass
        cp16(dst + (u32)(((kt * 8 + mt) << 9) + (part << 4)),
             (const char*)zfr + ((((size_t)(rt0 + mt) * 32 + kp) << 9) + (part << 4)));
    }
    #pragma unroll
    for (int t2 = 0; t2 < 4; t2++) {
        int t = tid + t2 * 256;
        int tile = t >> 4, part = t & 15;
        int kt = tile >> 4, nt = tile & 15;
        int ktg = ch * 4 + kt;                   // 0..63: hi then lo
        cp16(dst + 16384u + (u32)(((kt * 16 + nt) << 8) + (part << 4)),
             (const char*)efr + ((((size_t)(cb * 16 + nt) * 64 + ktg) << 8) + (part << 4)));
    }
    asm volatile("cp.async.commit_group;");
}

__global__ void __launch_bounds__(256, 2)
k_mma()
{
    extern __shared__ float smf[];
    __shared__ float en_s[128];
    __shared__ float sd[2][128], ss[2][128];
    __shared__ int   si[2][128];

    const int tid = threadIdx.x;
    const int lane = tid & 31, wid = tid >> 5;
    const int warp_m = wid & 3, warp_n = wid >> 2;
    const int cb = blockIdx.x;             // 0..7 (fast dim -> L2 reuse of zfr)
    const int rb = blockIdx.y;             // 0..255
    const int r0 = rb * 128, rt0 = rb * 8;
    const u32 base = smem_u32(smf);

    if (tid < 128) en_s[tid] = g_enorm[cb * 128 + tid];

    float d[2][8][4];
    #pragma unroll
    for (int m = 0; m < 2; m++)
        #pragma unroll
        for (int n = 0; n < 8; n++)
            #pragma unroll
            for (int q = 0; q < 4; q++) d[m][n][q] = 0.0f;

    load_chunk(base, 0, 0, rt0, cb, tid);
    load_chunk(base, 1, 1, rt0, cb, tid);

    int buf = 0;
    for (int ch = 0; ch < NCHUNK; ch++) {
        if (ch < NCHUNK - 1) asm volatile("cp.async.wait_group 1;");
        else                 asm volatile("cp.async.wait_group 0;");
        __syncthreads();
        if (ch + 2 < NCHUNK) {
            int nbuf = buf + 2; if (nbuf >= NSTAGE) nbuf -= NSTAGE;
            load_chunk(base, nbuf, ch + 2, rt0, cb, tid);
        }

        const float* aS = smf + buf * (STAGE_BYTES / 4);
        const float* bS = aS + 4096;
        #pragma unroll
        for (int kt = 0; kt < 4; kt++) {
            uint4 a[2];
            uint2 bf[8];
            #pragma unroll
            for (int m = 0; m < 2; m++)
                a[m] = *(const uint4*)(aS + ((((kt * 8 + warp_m * 2 + m) << 5) + lane) << 2));
            #pragma unroll
            for (int n = 0; n < 8; n++)
                bf[n] = *(const uint2*)(bS + ((((kt * 16 + warp_n * 8 + n) << 5) + lane) << 1));
            #pragma unroll
            for (int m = 0; m < 2; m++)
                #pragma unroll
                for (int n = 0; n < 8; n++)
                    mma8(d[m][n], a[m], bf[n]);
        }
        if (++buf >= NSTAGE) buf = 0;
    }

    // epilogue: dist = acc + ||e||^2 ; best + second-best per row
    const int g = lane >> 2, tq = lane & 3;
    const int wm0 = warp_m * 32, wn0 = warp_n * 64;
    #pragma unroll
    for (int m = 0; m < 2; m++) {
        #pragma unroll
        for (int h = 0; h < 2; h++) {
            float b1 = FLT_MAX, b2 = FLT_MAX; int i1 = 0x7fffffff;
            #pragma unroll
            for (int n = 0; n < 8; n++) {
                int cl = wn0 + n * 8 + 2 * tq;
                float v0 = d[m][n][2 * h]     + en_s[cl];
                float v1 = d[m][n][2 * h + 1] + en_s[cl + 1];
                int k0 = cb * 128 + cl;
                upd(b1, b2, i1, v0, k0);
                upd(b1, b2, i1, v1, k0 + 1);
            }
            #pragma unroll
            for (int s = 1; s <= 2; s <<= 1) {
                float ob1 = __shfl_xor_sync(0xffffffffu, b1, s);
                float ob2 = __shfl_xor_sync(0xffffffffu, b2, s);
                int   oi1 = __shfl_xor_sync(0xffffffffu, i1, s);
                if (ob1 < b1 || (ob1 == b1 && oi1 < i1)) {
                    b2 = fminf(b1, ob2); b1 = ob1; i1 = oi1;
                } else b2 = fminf(b2, ob1);
            }
            if (tq == 0) {
                int rl = wm0 + m * 16 + h * 8 + g;
                sd[warp_n][rl] = b1; ss[warp_n][rl] = b2; si[warp_n][rl] = i1;
            }
        }
    }
    __syncthreads();
    if (tid < 128) {
        float b1 = sd[0][tid], b2 = ss[0][tid]; int i1 = si[0][tid];
        float ob1 = sd[1][tid], ob2 = ss[1][tid]; int oi1 = si[1][tid];
        if (ob1 < b1 || (ob1 == b1 && oi1 < i1)) {
            b2 = fminf(b1, ob2); b1 = ob1; i1 = oi1;
        } else b2 = fminf(b2, ob1);
        int row = r0 + tid;
        g_pd[cb * N_ROWS + row] = b1;
        g_ps[cb * N_ROWS + row] = b2;
        g_pi[cb * N_ROWS + row] = i1;
    }
}

// ---------------------------------------------------------------------------
// combine partials; flag ambiguous rows
// ---------------------------------------------------------------------------
__global__ void k_pick(float* __restrict__ out_idx_f) {
    int row = blockIdx.x * 256 + threadIdx.x;
    float best = FLT_MAX, b2g = FLT_MAX;
    int bidx = 0x7fffffff;
    #pragma unroll
    for (int cb = 0; cb < NCB; cb++) {
        float d1 = g_pd[cb * N_ROWS + row];
        int   k1 = g_pi[cb * N_ROWS + row];
        float d2 = g_ps[cb * N_ROWS + row];
        if (d1 < best || (d1 == best && k1 < bidx)) {
            b2g = fminf(b2g, best); best = d1; bidx = k1;
        } else b2g = fminf(b2g, d1);
        b2g = fminf(b2g, d2);
    }
    g_idx[row] = bidx;
    out_idx_f[row] = (float)bidx;
    if (b2g - best < GAP_TH) {
        int p = atomicAdd(&g_nflag, 1);
        g_flagrows[p] = row;
    }
}

// ---------------------------------------------------------------------------
// exact fp32 recompute for ambiguous rows (reads z_e directly)
// ---------------------------------------------------------------------------
__global__ void k_fixup(const float* __restrict__ z_e,
                        const float* __restrict__ emb,
                        float* __restrict__ out_idx_f) {
    __shared__ float zs[256];
    __shared__ float wd[8];
    __shared__ int   wk[8];
    int tid = threadIdx.x, wid = tid >> 5, lane = tid & 31;
    int nf = g_nflag;
    for (int f = blockIdx.x; f < nf; f += gridDim.x) {
        int row = g_flagrows[f];
        __syncthreads();
        zs[tid] = z_e[(((size_t)((row >> 10) * C_DIM + tid)) << 10) + (row & 1023)];
        __syncthreads();
        float bd = FLT_MAX; int bk = 0x7fffffff;
        for (int k = wid; k < K_CODES; k += 8) {
            const float* er = emb + (size_t)k * C_DIM;
            float acc = 0.0f;
            #pragma unroll
            for (int cc = 0; cc < 8; cc++) {
                int c = cc * 32 + lane;
                acc += zs[c] * er[c];
            }
            #pragma unroll
            for (int m = 16; m; m >>= 1) acc += __shfl_xor_sync(0xffffffffu, acc, m);
            if (lane == 0) {
                float d = g_enorm[k] - 2.0f * acc;
                if (d < bd || (d == bd && k < bk)) { bd = d; bk = k; }
            }
        }
        if (lane == 0) { wd[wid] = bd; wk[wid] = bk; }
        __syncthreads();
        if (tid == 0) {
            float B = FLT_MAX; int K = 0x7fffffff;
            #pragma unroll
            for (int w = 0; w < 8; w++)
                if (wd[w] < B || (wd[w] == B && wk[w] < K)) { B = wd[w]; K = wk[w]; }
            g_idx[row] = K;
            out_idx_f[row] = (float)K;
        }
    }
}

// ---------------------------------------------------------------------------
// gather + loss
// ---------------------------------------------------------------------------
#define SMEM_GATHER (128 * 257 * 4)
__global__ void __launch_bounds__(256)
k_gather(const float* __restrict__ z_e, const float* __restrict__ emb,
         float* __restrict__ res)
{
    extern __shared__ float esm[];
    __shared__ int   idx_sm[128];
    __shared__ float wsum[8];

    const int tid = threadIdx.x;
    const int r0 = blockIdx.x * 128;
    const int b = r0 >> 10, hw0 = r0 & 1023;

    if (tid < 128) idx_sm[tid] = g_idx[r0 + tid];
    __syncthreads();
    for (int i = tid; i < 128 * 256; i += 256) {
        int r = i >> 8, c = i & 255;
        esm[r * 257 + c] = emb[idx_sm[r] * C_DIM + c];
    }
    __syncthreads();

    float acc = 0.0f;
    const int r = tid & 127, chalf = tid >> 7;
    for (int cc = 0; cc < 256; cc += 2) {
        int c = cc + chalf;
        float v = esm[r * 257 + c];
        size_t gi = (((size_t)(b * C_DIM + c)) << 10) + hw0 + r;
        float zv = z_e[gi];
        res[gi] = v;
        float df = v - zv;
        acc += df * df;
    }
    #pragma unroll
    for (int m = 16; m; m >>= 1) acc += __shfl_xor_sync(0xffffffffu, acc, m);
    if ((tid & 31) == 0) wsum[tid >> 5] = acc;
    __syncthreads();
    if (tid == 0) {
        float s = 0.0f;
        #pragma unroll
        for (int w = 0; w < 8; w++) s += wsum[w];
        g_partial[blockIdx.x] = s;
    }
}

__global__ void k_loss(float* __restrict__ out_loss) {
    __shared__ float s[256];
    int tid = threadIdx.x;
    s[tid] = g_partial[tid];
    __syncthreads();
    for (int st = 128; st > 0; st >>= 1) {
        if (tid < st) s[tid] += s[tid + st];
        __syncthreads();
    }
    if (tid == 0) out_loss[0] = 1.25f * (s[0] / 8388608.0f);
}

// ---------------------------------------------------------------------------
extern "C" void kernel_launch(void* const* d_in, const int* in_sizes, int n_in,
                              void* d_out, int out_size)
{
    const float* z_e = (const float*)d_in[0];
    const float* emb = (const float*)d_in[1];

    float* out  = (float*)d_out;
    float* res  = out;
    float* loss = out + 8388608;
    float* idxf = out + 8388609;

    cudaFuncSetAttribute(k_mma,    cudaFuncAttributeMaxDynamicSharedMemorySize, SMEM_MMA);
    cudaFuncSetAttribute(k_gather, cudaFuncAttributeMaxDynamicSharedMemorySize, SMEM_GATHER);

    k_prep_z <<<N_ROWS / 32, 256>>>(z_e);
    k_prep_e <<<128, 256>>>(emb);
    k_enorm  <<<K_CODES / 8, 256>>>(emb);
    k_mma    <<<dim3(NCB, N_ROWS / 128), 256, SMEM_MMA>>>();
    k_pick   <<<N_ROWS / 256, 256>>>(idxf);
    k_fixup  <<<256, 256>>>(z_e, emb, idxf);
    k_gather <<<N_ROWS / 128, 256, SMEM_GATHER>>>(z_e, emb, res);
    k_loss   <<<1, 256>>>(loss);
}

// round 7
// speedup vs baseline: 1.7261x; 1.7261x over previous
#include <cuda_runtime.h>
#include <cstdint>
#include <cfloat>

typedef unsigned long long ull;
typedef unsigned int u32;

#define N_ROWS  32768
#define C_DIM   256
#define K_CODES 1024
#define NCB     8          // code-blocks of 128
#define NCHUNK  8          // chunk = 4 kt of A against B_hi and B_lo
#define E2      0.2f       // 2*E, E=0.1 >= 11 sigma of dropped-term error
#define STAGE_BYTES 49152  // A 16KB + Bhi 16KB + Blo 16KB
#define SMEM_MMA (2 * STAGE_BYTES)   // 98304

// fragment-native global layouts
// zfr: [row_tile(2048)][kt(32) hi only][lane 32][reg 4]
// efr: [code_tile(128)][klog(64: hi,lo)][lane 32][reg 2]
__device__ float zfr[(size_t)(N_ROWS / 16) * 32 * 128];
__device__ float efr[(size_t)(K_CODES / 8) * 64 * 64];
__device__ float g_enorm[K_CODES];
__device__ int   g_idx[N_ROWS];
__device__ float g_pd[NCB * N_ROWS];
__device__ float g_ps[NCB * N_ROWS];
__device__ int   g_pi[NCB * N_ROWS];
__device__ int   g_nref, g_nfull;
__device__ int   g_refrows[N_ROWS];
__device__ int   g_fullrows[N_ROWS];
__device__ int   g_cand[N_ROWS * 8];
__device__ unsigned char g_ccnt[N_ROWS];
__device__ float g_partial[256];

// ---------------- helpers ----------------
__device__ __forceinline__ u32 smem_u32(const void* p) {
    return (u32)__cvta_generic_to_shared(p);
}
__device__ __forceinline__ void cp16(u32 dst, const void* src) {
    asm volatile("cp.async.cg.shared.global [%0], [%1], 16;" :: "r"(dst), "l"(src));
}
__device__ __forceinline__ float tf32_rna(float v) {
    u32 r; asm("cvt.rna.satfinite.tf32.f32 %0, %1;" : "=r"(r) : "f"(v));
    return __uint_as_float(r);
}
__device__ __forceinline__ void mma8(float* d, uint4 a, uint2 b) {
    asm("mma.sync.aligned.m16n8k8.row.col.f32.tf32.tf32.f32 "
        "{%0,%1,%2,%3}, {%4,%5,%6,%7}, {%8,%9}, {%0,%1,%2,%3};"
        : "+f"(d[0]), "+f"(d[1]), "+f"(d[2]), "+f"(d[3])
        : "r"(a.x), "r"(a.y), "r"(a.z), "r"(a.w), "r"(b.x), "r"(b.y));
}
__device__ __forceinline__ void upd(float& b1, float& b2, int& i1, float v, int k) {
    if (v < b1 || (v == b1 && k < i1)) { b2 = b1; b1 = v; i1 = k; }
    else if (v < b2) b2 = v;
}

// ---------------------------------------------------------------------------
// prep: z -> fragment layout (hi only)
// ---------------------------------------------------------------------------
__global__ void k_prep_z(const float* __restrict__ z_e) {
    __shared__ float t[32 * 260];
    int tid = threadIdx.x;
    int r0 = blockIdx.x * 32;
    int b = r0 >> 10, hw0 = r0 & 1023;
    if (blockIdx.x == 0 && tid == 0) { g_nref = 0; g_nfull = 0; }
    for (int i = tid; i < 32 * 256; i += 256) {
        int c = i >> 5, r = i & 31;
        t[r * 260 + c] = z_e[(((size_t)(b * C_DIM + c)) << 10) + hw0 + r];
    }
    __syncthreads();
    int rt0 = r0 >> 4;
    for (int i = tid; i < 32 * 256; i += 256) {
        int within = i & 127;
        int tile = i >> 7;
        int rtl = tile >> 5;
        int kt  = tile & 31;
        int lane = within >> 2, reg = within & 3;
        int rl = rtl * 16 + (lane >> 2) + ((reg & 1) << 3);
        int cmod = (kt << 3) + (lane & 3) + ((reg >> 1) << 2);
        float v = t[rl * 260 + cmod];
        zfr[(((size_t)(rt0 + rtl) * 32 + kt) << 7) + within] = tf32_rna(v);
    }
}

// ---------------------------------------------------------------------------
// prep: e -> fragment layout [hi, lo] of (-2*emb); also codebook norms
// ---------------------------------------------------------------------------
__global__ void k_prep_e(const float* __restrict__ emb) {
    size_t base = (size_t)blockIdx.x * 4096;
    for (int j = threadIdx.x; j < 4096; j += 256) {
        size_t idx = base + j;
        int within = (int)(idx & 63);
        int tile = (int)(idx >> 6);
        int nt = tile >> 6, kt = tile & 63;
        int lane = within >> 1, reg = within & 1;
        int code = nt * 8 + (lane >> 2);
        int sec = kt >> 5;
        int cmod = ((kt & 31) << 3) + (lane & 3) + (reg << 2);
        float v = -2.0f * emb[code * 256 + cmod];
        float hi = tf32_rna(v);
        efr[idx] = sec ? tf32_rna(v - hi) : hi;
    }
    // norms: warp per code (128 blocks * 8 warps = 1024 codes)
    int wid = threadIdx.x >> 5, lane = threadIdx.x & 31;
    int code = blockIdx.x * 8 + wid;
    const float4* p = (const float4*)(emb + code * C_DIM);
    float4 a = p[lane];
    float4 b = p[lane + 32];
    float s = a.x*a.x + a.y*a.y + a.z*a.z + a.w*a.w
            + b.x*b.x + b.y*b.y + b.z*b.z + b.w*b.w;
    #pragma unroll
    for (int m = 16; m; m >>= 1) s += __shfl_xor_sync(0xffffffffu, s, m);
    if (lane == 0) g_enorm[code] = s;
}

// ---------------------------------------------------------------------------
// main: tf32 mma.sync GEMM (hi*hi + hi*lo) + argmin (best + second-best)
// CTA 128 rows x 128 codes, 8 warps (4 row x 2 col), warp tile 32x64.
// Stage = {A chunk, B_hi chunk, B_lo chunk}; A reused for both B sections.
// ---------------------------------------------------------------------------
__device__ __forceinline__ void load_chunk(u32 base, int buf, int ch,
                                           int rt0, int cb, int tid)
{
    u32 dst = base + (u32)buf * STAGE_BYTES;
    #pragma unroll
    for (int t2 = 0; t2 < 4; t2++) {           // A: 4 kt x 8 mt x 512B
        int t = tid + t2 * 256;
        int tile = t >> 5, part = t & 31;
        int kt = tile >> 3, mt = tile & 7;
        cp16(dst + (u32)(((kt * 8 + mt) << 9) + (part << 4)),
             (const char*)zfr + ((((size_t)(rt0 + mt) * 32 + ch * 4 + kt) << 9) + (part << 4)));
    }
    #pragma unroll
    for (int t2 = 0; t2 < 4; t2++) {           // B_hi: 4 kt x 16 nt x 256B
        int t = tid + t2 * 256;
        int tile = t >> 4, part = t & 15;
        int kt = tile >> 4, nt = tile & 15;
        cp16(dst + 16384u + (u32)(((kt * 16 + nt) << 8) + (part << 4)),
             (const char*)efr + ((((size_t)(cb * 16 + nt) * 64 + ch * 4 + kt) << 8) + (part << 4)));
    }
    #pragma unroll
    for (int t2 = 0; t2 < 4; t2++) {           // B_lo
        int t = tid + t2 * 256;
        int tile = t >> 4, part = t & 15;
        int kt = tile >> 4, nt = tile & 15;
        cp16(dst + 32768u + (u32)(((kt * 16 + nt) << 8) + (part << 4)),
             (const char*)efr + ((((size_t)(cb * 16 + nt) * 64 + 32 + ch * 4 + kt) << 8) + (part << 4)));
    }
    asm volatile("cp.async.commit_group;");
}

__global__ void __launch_bounds__(256, 2)
k_mma()
{
    extern __shared__ float smf[];
    __shared__ float en_s[128];
    __shared__ float sd[2][128], ss[2][128];
    __shared__ int   si[2][128];

    const int tid = threadIdx.x;
    const int lane = tid & 31, wid = tid >> 5;
    const int warp_m = wid & 3, warp_n = wid >> 2;
    const int cb = blockIdx.x;             // fast dim -> L2 reuse of zfr
    const int rb = blockIdx.y;
    const int r0 = rb * 128, rt0 = rb * 8;
    const u32 base = smem_u32(smf);

    if (tid < 128) en_s[tid] = g_enorm[cb * 128 + tid];

    float d[2][8][4];
    #pragma unroll
    for (int m = 0; m < 2; m++)
        #pragma unroll
        for (int n = 0; n < 8; n++)
            #pragma unroll
            for (int q = 0; q < 4; q++) d[m][n][q] = 0.0f;

    load_chunk(base, 0, 0, rt0, cb, tid);
    load_chunk(base, 1, 1, rt0, cb, tid);

    for (int ch = 0; ch < NCHUNK; ch++) {
        const int buf = ch & 1;
        if (ch < NCHUNK - 1) asm volatile("cp.async.wait_group 1;");
        else                 asm volatile("cp.async.wait_group 0;");
        __syncthreads();

        const float* aS  = smf + buf * (STAGE_BYTES / 4);
        const float* bhS = aS + 4096;
        const float* blS = aS + 8192;
        #pragma unroll
        for (int kt = 0; kt < 4; kt++) {
            uint4 a[2];
            uint2 bf[8];
            #pragma unroll
            for (int m = 0; m < 2; m++)
                a[m] = *(const uint4*)(aS + ((((kt * 8 + warp_m * 2 + m) << 5) + lane) << 2));
            #pragma unroll
            for (int n = 0; n < 8; n++)
                bf[n] = *(const uint2*)(bhS + ((((kt * 16 + warp_n * 8 + n) << 5) + lane) << 1));
            #pragma unroll
            for (int m = 0; m < 2; m++)
                #pragma unroll
                for (int n = 0; n < 8; n++)
                    mma8(d[m][n], a[m], bf[n]);
            #pragma unroll
            for (int n = 0; n < 8; n++)
                bf[n] = *(const uint2*)(blS + ((((kt * 16 + warp_n * 8 + n) << 5) + lane) << 1));
            #pragma unroll
            for (int m = 0; m < 2; m++)
                #pragma unroll
                for (int n = 0; n < 8; n++)
                    mma8(d[m][n], a[m], bf[n]);
        }
        __syncthreads();                      // all warps done reading buf
        if (ch + 2 < NCHUNK) load_chunk(base, buf, ch + 2, rt0, cb, tid);
    }

    // epilogue: dist = acc + ||e||^2 ; best + second-best per row
    const int g = lane >> 2, tq = lane & 3;
    const int wm0 = warp_m * 32, wn0 = warp_n * 64;
    #pragma unroll
    for (int m = 0; m < 2; m++) {
        #pragma unroll
        for (int h = 0; h < 2; h++) {
            float b1 = FLT_MAX, b2 = FLT_MAX; int i1 = 0x7fffffff;
            #pragma unroll
            for (int n = 0; n < 8; n++) {
                int cl = wn0 + n * 8 + 2 * tq;
                float v0 = d[m][n][2 * h]     + en_s[cl];
                float v1 = d[m][n][2 * h + 1] + en_s[cl + 1];
                int k0 = cb * 128 + cl;
                upd(b1, b2, i1, v0, k0);
                upd(b1, b2, i1, v1, k0 + 1);
            }
            #pragma unroll
            for (int s = 1; s <= 2; s <<= 1) {
                float ob1 = __shfl_xor_sync(0xffffffffu, b1, s);
                float ob2 = __shfl_xor_sync(0xffffffffu, b2, s);
                int   oi1 = __shfl_xor_sync(0xffffffffu, i1, s);
                if (ob1 < b1 || (ob1 == b1 && oi1 < i1)) {
                    b2 = fminf(b1, ob2); b1 = ob1; i1 = oi1;
                } else b2 = fminf(b2, ob1);
            }
            if (tq == 0) {
                int rl = wm0 + m * 16 + h * 8 + g;
                sd[warp_n][rl] = b1; ss[warp_n][rl] = b2; si[warp_n][rl] = i1;
            }
        }
    }
    __syncthreads();
    if (tid < 128) {
        float b1 = sd[0][tid], b2 = ss[0][tid]; int i1 = si[0][tid];
        float ob1 = sd[1][tid], ob2 = ss[1][tid]; int oi1 = si[1][tid];
        if (ob1 < b1 || (ob1 == b1 && oi1 < i1)) {
            b2 = fminf(b1, ob2); b1 = ob1; i1 = oi1;
        } else b2 = fminf(b2, ob1);
        int row = r0 + tid;
        g_pd[cb * N_ROWS + row] = b1;
        g_ps[cb * N_ROWS + row] = b2;
        g_pi[cb * N_ROWS + row] = i1;
    }
}

// ---------------------------------------------------------------------------
// pick: default winner; route rows to refine (candidates) or full scan
// ---------------------------------------------------------------------------
__global__ void k_pick2(float* __restrict__ out_idx_f) {
    int row = blockIdx.x * 256 + threadIdx.x;
    float v1[8], v2[8]; int i1[8];
    float V1 = FLT_MAX; int bi = 0x7fffffff;
    #pragma unroll
    for (int cb = 0; cb < NCB; cb++) {
        v1[cb] = g_pd[cb * N_ROWS + row];
        v2[cb] = g_ps[cb * N_ROWS + row];
        i1[cb] = g_pi[cb * N_ROWS + row];
        if (v1[cb] < V1 || (v1[cb] == V1 && i1[cb] < bi)) { V1 = v1[cb]; bi = i1[cb]; }
    }
    g_idx[row] = bi;
    out_idx_f[row] = (float)bi;
    float th = V1 + E2;
    bool unc = false; int nc = 0; int cands[8];
    #pragma unroll
    for (int cb = 0; cb < NCB; cb++) {
        if (v2[cb] < th) unc = true;
        if (v1[cb] < th) cands[nc++] = i1[cb];
    }
    if (unc) {
        int p = atomicAdd(&g_nfull, 1);
        g_fullrows[p] = row;
    } else if (nc > 1) {
        int p = atomicAdd(&g_nref, 1);
        g_refrows[p] = row;
        g_ccnt[row] = (unsigned char)nc;
        #pragma unroll
        for (int q = 0; q < 8; q++) if (q < nc) g_cand[row * 8 + q] = cands[q];
    }
}

// ---------------------------------------------------------------------------
// refine: exact fp32 distance over <=8 candidates (warp per row)
// ---------------------------------------------------------------------------
__global__ void __launch_bounds__(256)
k_refine(const float* __restrict__ z_e, const float* __restrict__ emb,
         float* __restrict__ out_idx_f)
{
    int lane = threadIdx.x & 31;
    int gw = blockIdx.x * 8 + (threadIdx.x >> 5);
    int nr = g_nref;
    for (int j = gw; j < nr; j += 2048) {
        int row = g_refrows[j];
        int b = row >> 10, hw = row & 1023;
        float zreg[8];
        #pragma unroll
        for (int cc = 0; cc < 8; cc++)
            zreg[cc] = z_e[(((size_t)(b * C_DIM + cc * 32 + lane)) << 10) + hw];
        int nc = g_ccnt[row];
        float bd = FLT_MAX; int bk = 0x7fffffff;
        for (int ci = 0; ci < nc; ci++) {
            int k = g_cand[row * 8 + ci];
            const float* er = emb + (size_t)k * C_DIM;
            float acc = 0.0f;
            #pragma unroll
            for (int cc = 0; cc < 8; cc++)
                acc += zreg[cc] * er[cc * 32 + lane];
            #pragma unroll
            for (int m = 16; m; m >>= 1) acc += __shfl_xor_sync(0xffffffffu, acc, m);
            float d = g_enorm[k] - 2.0f * acc;
            if (d < bd || (d == bd && k < bk)) { bd = d; bk = k; }
        }
        if (lane == 0) { g_idx[row] = bk; out_idx_f[row] = (float)bk; }
    }
}

// ---------------------------------------------------------------------------
// full exact scan for coverage-uncertain rows
// ---------------------------------------------------------------------------
__global__ void k_fixup(const float* __restrict__ z_e,
                        const float* __restrict__ emb,
                        float* __restrict__ out_idx_f) {
    __shared__ float zs[256];
    __shared__ float wd[8];
    __shared__ int   wk[8];
    int tid = threadIdx.x, wid = tid >> 5, lane = tid & 31;
    int nf = g_nfull;
    for (int f = blockIdx.x; f < nf; f += gridDim.x) {
        int row = g_fullrows[f];
        __syncthreads();
        zs[tid] = z_e[(((size_t)((row >> 10) * C_DIM + tid)) << 10) + (row & 1023)];
        __syncthreads();
        float bd = FLT_MAX; int bk = 0x7fffffff;
        for (int k = wid; k < K_CODES; k += 8) {
            const float* er = emb + (size_t)k * C_DIM;
            float acc = 0.0f;
            #pragma unroll
            for (int cc = 0; cc < 8; cc++) {
                int c = cc * 32 + lane;
                acc += zs[c] * er[c];
            }
            #pragma unroll
            for (int m = 16; m; m >>= 1) acc += __shfl_xor_sync(0xffffffffu, acc, m);
            if (lane == 0) {
                float d = g_enorm[k] - 2.0f * acc;
                if (d < bd || (d == bd && k < bk)) { bd = d; bk = k; }
            }
        }
        if (lane == 0) { wd[wid] = bd; wk[wid] = bk; }
        __syncthreads();
        if (tid == 0) {
            float B = FLT_MAX; int K = 0x7fffffff;
            #pragma unroll
            for (int w = 0; w < 8; w++)
                if (wd[w] < B || (wd[w] == B && wk[w] < K)) { B = wd[w]; K = wk[w]; }
            g_idx[row] = K;
            out_idx_f[row] = (float)K;
        }
    }
}

// ---------------------------------------------------------------------------
// gather + loss
// ---------------------------------------------------------------------------
#define SMEM_GATHER (128 * 257 * 4)
__global__ void __launch_bounds__(256)
k_gather(const float* __restrict__ z_e, const float* __restrict__ emb,
         float* __restrict__ res)
{
    extern __shared__ float esm[];
    __shared__ int   idx_sm[128];
    __shared__ float wsum[8];

    const int tid = threadIdx.x;
    const int r0 = blockIdx.x * 128;
    const int b = r0 >> 10, hw0 = r0 & 1023;

    if (tid < 128) idx_sm[tid] = g_idx[r0 + tid];
    __syncthreads();
    for (int i = tid; i < 128 * 256; i += 256) {
        int r = i >> 8, c = i & 255;
        esm[r * 257 + c] = emb[idx_sm[r] * C_DIM + c];
    }
    __syncthreads();

    float acc = 0.0f;
    const int r = tid & 127, chalf = tid >> 7;
    for (int cc = 0; cc < 256; cc += 2) {
        int c = cc + chalf;
        float v = esm[r * 257 + c];
        size_t gi = (((size_t)(b * C_DIM + c)) << 10) + hw0 + r;
        float zv = z_e[gi];
        res[gi] = v;
        float df = v - zv;
        acc += df * df;
    }
    #pragma unroll
    for (int m = 16; m; m >>= 1) acc += __shfl_xor_sync(0xffffffffu, acc, m);
    if ((tid & 31) == 0) wsum[tid >> 5] = acc;
    __syncthreads();
    if (tid == 0) {
        float s = 0.0f;
        #pragma unroll
        for (int w = 0; w < 8; w++) s += wsum[w];
        g_partial[blockIdx.x] = s;
    }
}

__global__ void k_loss(float* __restrict__ out_loss) {
    __shared__ float s[256];
    int tid = threadIdx.x;
    s[tid] = g_partial[tid];
    __syncthreads();
    for (int st = 128; st > 0; st >>= 1) {
        if (tid < st) s[tid] += s[tid + st];
        __syncthreads();
    }
    if (tid == 0) out_loss[0] = 1.25f * (s[0] / 8388608.0f);
}

// ---------------------------------------------------------------------------
extern "C" void kernel_launch(void* const* d_in, const int* in_sizes, int n_in,
                              void* d_out, int out_size)
{
    const float* z_e = (const float*)d_in[0];
    const float* emb = (const float*)d_in[1];

    float* out  = (float*)d_out;
    float* res  = out;
    float* loss = out + 8388608;
    float* idxf = out + 8388609;

    cudaFuncSetAttribute(k_mma,    cudaFuncAttributeMaxDynamicSharedMemorySize, SMEM_MMA);
    cudaFuncSetAttribute(k_gather, cudaFuncAttributeMaxDynamicSharedMemorySize, SMEM_GATHER);

    k_prep_z <<<N_ROWS / 32, 256>>>(z_e);
    k_prep_e <<<K_CODES / 8, 256>>>(emb);
    k_mma    <<<dim3(NCB, N_ROWS / 128), 256, SMEM_MMA>>>();
    k_pick2  <<<N_ROWS / 256, 256>>>(idxf);
    k_refine <<<256, 256>>>(z_e, emb, idxf);
    k_fixup  <<<256, 256>>>(z_e, emb, idxf);
    k_gather <<<N_ROWS / 128, 256, SMEM_GATHER>>>(z_e, emb, res);
    k_loss   <<<1, 256>>>(loss);
}

// round 8
// speedup vs baseline: 1.8133x; 1.0505x over previous
#include <cuda_runtime.h>
#include <cstdint>
#include <cfloat>

typedef unsigned long long ull;
typedef unsigned int u32;

#define N_ROWS  32768
#define C_DIM   256
#define K_CODES 1024
#define NCB     8          // code-blocks of 128
#define NCHUNK  8          // chunks of 32 c (K logical = 256, hi*hi only)
#define E2      0.5f       // 2*E; E=0.25 >= 15 sigma of hi-only error (rms ~2.2e-2)
#define NSTAGE  3
#define STAGE_BYTES 49152  // A 32KB + B 16KB
#define SMEM_MMA (NSTAGE * STAGE_BYTES)   // 147456
#define SMEM_POST (128 * 257 * 4)         // esm

// fragment-native layouts
// zfr: [row_tile(2048)][kt(32)][lane 32][reg 4]  (tf32 hi)
// efr: [code_tile(128)][kt(32)][lane 32][reg 2]  (tf32 hi of -2*emb)
__device__ float zfr[(size_t)(N_ROWS / 16) * 32 * 128];
__device__ float efr[(size_t)(K_CODES / 8) * 32 * 64];
__device__ float embT[C_DIM * K_CODES];    // [c][k] = -2*emb[k][c], exact fp32
__device__ float g_enorm[K_CODES];
__device__ float g_pd[NCB * N_ROWS];
__device__ float g_ps[NCB * N_ROWS];
__device__ int   g_pi[NCB * N_ROWS];
__device__ float g_partial[256];

// ---------------- helpers ----------------
__device__ __forceinline__ u32 smem_u32(const void* p) {
    return (u32)__cvta_generic_to_shared(p);
}
__device__ __forceinline__ void cp16(u32 dst, const void* src) {
    asm volatile("cp.async.cg.shared.global [%0], [%1], 16;" :: "r"(dst), "l"(src));
}
__device__ __forceinline__ float tf32_rna(float v) {
    u32 r; asm("cvt.rna.satfinite.tf32.f32 %0, %1;" : "=r"(r) : "f"(v));
    return __uint_as_float(r);
}
__device__ __forceinline__ void mma8(float* d, uint4 a, uint2 b) {
    asm("mma.sync.aligned.m16n8k8.row.col.f32.tf32.tf32.f32 "
        "{%0,%1,%2,%3}, {%4,%5,%6,%7}, {%8,%9}, {%0,%1,%2,%3};"
        : "+f"(d[0]), "+f"(d[1]), "+f"(d[2]), "+f"(d[3])
        : "r"(a.x), "r"(a.y), "r"(a.z), "r"(a.w), "r"(b.x), "r"(b.y));
}
__device__ __forceinline__ void upd(float& b1, float& b2, int& i1, float v, int k) {
    if (v < b1 || (v == b1 && k < i1)) { b2 = b1; b1 = v; i1 = k; }
    else if (v < b2) b2 = v;
}

// ---------------------------------------------------------------------------
// prep: blocks [0,1024) convert z; blocks [1024,1152) convert emb (+norms,embT)
// ---------------------------------------------------------------------------
__global__ void __launch_bounds__(256)
k_prep(const float* __restrict__ z_e, const float* __restrict__ emb)
{
    __shared__ float t[32 * 260];
    const int tid = threadIdx.x;
    if (blockIdx.x < 1024) {
        int r0 = blockIdx.x * 32;
        int b = r0 >> 10, hw0 = r0 & 1023;
        for (int i = tid; i < 32 * 256; i += 256) {
            int c = i >> 5, r = i & 31;
            t[r * 260 + c] = z_e[(((size_t)(b * C_DIM + c)) << 10) + hw0 + r];
        }
        __syncthreads();
        int rt0 = r0 >> 4;
        for (int i = tid; i < 32 * 256; i += 256) {
            int within = i & 127;
            int tile = i >> 7;
            int rtl = tile >> 5;
            int kt  = tile & 31;
            int lane = within >> 2, reg = within & 3;
            int rl = rtl * 16 + (lane >> 2) + ((reg & 1) << 3);
            int cmod = (kt << 3) + (lane & 3) + ((reg >> 1) << 2);
            zfr[(((size_t)(rt0 + rtl) * 32 + kt) << 7) + within] = tf32_rna(t[rl * 260 + cmod]);
        }
    } else {
        int ct = blockIdx.x - 1024;        // code tile, 8 codes
        int k0 = ct * 8;
        for (int j = tid; j < 2048; j += 256) {
            int within = j & 63, kt = j >> 6;
            int lane = within >> 1, reg = within & 1;
            int code = k0 + (lane >> 2);
            int cmod = kt * 8 + (lane & 3) + reg * 4;
            efr[(size_t)(ct * 32 + kt) * 64 + within] = tf32_rna(-2.0f * emb[code * C_DIM + cmod]);
        }
        for (int j = tid; j < 2048; j += 256) {
            int c = j >> 3, kk = j & 7;
            embT[c * K_CODES + k0 + kk] = -2.0f * emb[(k0 + kk) * C_DIM + c];
        }
        int wid = tid >> 5, lane = tid & 31;
        int code = k0 + wid;
        const float4* p = (const float4*)(emb + code * C_DIM);
        float4 a = p[lane];
        float4 b = p[lane + 32];
        float s = a.x*a.x + a.y*a.y + a.z*a.z + a.w*a.w
                + b.x*b.x + b.y*b.y + b.z*b.z + b.w*b.w;
        #pragma unroll
        for (int m = 16; m; m >>= 1) s += __shfl_xor_sync(0xffffffffu, s, m);
        if (lane == 0) g_enorm[code] = s;
    }
}

// ---------------------------------------------------------------------------
// main: tf32 mma.sync GEMM (hi*hi) + argmin (best + second-best)
// CTA 256 rows x 128 codes, 8 warps (4 row x 2 col), warp tile 64x64.
// 3-stage cp.async ring, 1 CTA/SM.
// ---------------------------------------------------------------------------
__device__ __forceinline__ void load_chunk(u32 base, int buf, int ch,
                                           int rt0, int cb, int tid)
{
    u32 dst = base + (u32)buf * STAGE_BYTES;
    #pragma unroll
    for (int t2 = 0; t2 < 8; t2++) {           // A: 4kt x 16mt x 512B
        int t = tid + t2 * 256;
        int tile = t >> 5, part = t & 31;
        int kt = tile >> 4, mt = tile & 15;
        cp16(dst + (u32)((tile << 9) + (part << 4)),
             (const char*)zfr + ((((size_t)(rt0 + mt) * 32 + ch * 4 + kt) << 9) + (part << 4)));
    }
    #pragma unroll
    for (int t2 = 0; t2 < 4; t2++) {           // B: 4kt x 16nt x 256B
        int t = tid + t2 * 256;
        int tile = t >> 4, part = t & 15;
        int kt = tile >> 4, nt = tile & 15;
        cp16(dst + 32768u + (u32)((tile << 8) + (part << 4)),
             (const char*)efr + ((((size_t)(cb * 16 + nt) * 32 + ch * 4 + kt) << 8) + (part << 4)));
    }
    asm volatile("cp.async.commit_group;");
}

__global__ void __launch_bounds__(256, 1)
k_mma()
{
    extern __shared__ float smf[];
    __shared__ float en_s[128];
    __shared__ float sd[2][256], ss[2][256];
    __shared__ int   si[2][256];

    const int tid = threadIdx.x;
    const int lane = tid & 31, wid = tid >> 5;
    const int warp_m = wid & 3, warp_n = wid >> 2;
    const int cb = blockIdx.x;             // fast dim -> L2 reuse of zfr
    const int rb = blockIdx.y;
    const int r0 = rb * 256, rt0 = rb * 16;
    const u32 base = smem_u32(smf);

    if (tid < 128) en_s[tid] = g_enorm[cb * 128 + tid];

    float d[4][8][4];
    #pragma unroll
    for (int m = 0; m < 4; m++)
        #pragma unroll
        for (int n = 0; n < 8; n++)
            #pragma unroll
            for (int q = 0; q < 4; q++) d[m][n][q] = 0.0f;

    load_chunk(base, 0, 0, rt0, cb, tid);
    load_chunk(base, 1, 1, rt0, cb, tid);

    for (int ch = 0; ch < NCHUNK; ch++) {
        int buf = ch % NSTAGE;
        if (ch < NCHUNK - 1) asm volatile("cp.async.wait_group 1;");
        else                 asm volatile("cp.async.wait_group 0;");
        __syncthreads();
        if (ch + 2 < NCHUNK) load_chunk(base, (ch + 2) % NSTAGE, ch + 2, rt0, cb, tid);

        const float* aS = smf + buf * (STAGE_BYTES / 4);
        const float* bS = aS + 8192;
        #pragma unroll
        for (int kt = 0; kt < 4; kt++) {
            uint4 a[4];
            uint2 bf[8];
            #pragma unroll
            for (int m = 0; m < 4; m++)
                a[m] = *(const uint4*)(aS + (((kt * 16 + warp_m * 4 + m) << 7) + (lane << 2)));
            #pragma unroll
            for (int n = 0; n < 8; n++)
                bf[n] = *(const uint2*)(bS + (((kt * 16 + warp_n * 8 + n) << 6) + (lane << 1)));
            #pragma unroll
            for (int m = 0; m < 4; m++)
                #pragma unroll
                for (int n = 0; n < 8; n++)
                    mma8(d[m][n], a[m], bf[n]);
        }
    }

    // epilogue: dist = acc + ||e||^2 ; best + second-best per row
    const int g = lane >> 2, tq = lane & 3;
    const int wm0 = warp_m * 64, wn0 = warp_n * 64;
    #pragma unroll
    for (int m = 0; m < 4; m++) {
        #pragma unroll
        for (int h = 0; h < 2; h++) {
            float b1 = FLT_MAX, b2 = FLT_MAX; int i1 = 0x7fffffff;
            #pragma unroll
            for (int n = 0; n < 8; n++) {
                int cl = wn0 + n * 8 + 2 * tq;
                float v0 = d[m][n][2 * h]     + en_s[cl];
                float v1 = d[m][n][2 * h + 1] + en_s[cl + 1];
                int k0 = cb * 128 + cl;
                upd(b1, b2, i1, v0, k0);
                upd(b1, b2, i1, v1, k0 + 1);
            }
            #pragma unroll
            for (int s = 1; s <= 2; s <<= 1) {
                float ob1 = __shfl_xor_sync(0xffffffffu, b1, s);
                float ob2 = __shfl_xor_sync(0xffffffffu, b2, s);
                int   oi1 = __shfl_xor_sync(0xffffffffu, i1, s);
                if (ob1 < b1 || (ob1 == b1 && oi1 < i1)) {
                    b2 = fminf(b1, ob2); b1 = ob1; i1 = oi1;
                } else b2 = fminf(b2, ob1);
            }
            if (tq == 0) {
                int rl = wm0 + m * 16 + h * 8 + g;
                sd[warp_n][rl] = b1; ss[warp_n][rl] = b2; si[warp_n][rl] = i1;
            }
        }
    }
    __syncthreads();
    {
        float b1 = sd[0][tid], b2 = ss[0][tid]; int i1 = si[0][tid];
        float ob1 = sd[1][tid], ob2 = ss[1][tid]; int oi1 = si[1][tid];
        if (ob1 < b1 || (ob1 == b1 && oi1 < i1)) {
            b2 = fminf(b1, ob2); b1 = ob1; i1 = oi1;
        } else b2 = fminf(b2, ob1);
        int row = r0 + tid;
        g_pd[cb * N_ROWS + row] = b1;
        g_ps[cb * N_ROWS + row] = b2;
        g_pi[cb * N_ROWS + row] = i1;
    }
}

// ---------------------------------------------------------------------------
// post: pick + candidate refine + full-scan rescue + gather + loss partial.
// Block handles 128 rows (one b-slice). All exact math in fp32.
// ---------------------------------------------------------------------------
__global__ void __launch_bounds__(256)
k_post(const float* __restrict__ z_e, const float* __restrict__ emb,
       float* __restrict__ res, float* __restrict__ out_idx_f)
{
    extern __shared__ float esm[];           // 128 x 257
    __shared__ int   idx_sm[128];
    __shared__ int   full_list[128];
    __shared__ int   ref_list[128];
    __shared__ int   cand[128][8];
    __shared__ int   ccnt[128];
    __shared__ int   nfull_s, nref_s;
    __shared__ float zrow[256];
    __shared__ float wd[8]; __shared__ int wk[8];
    __shared__ float wsum[8];

    const int tid = threadIdx.x;
    const int wid = tid >> 5, lane = tid & 31;
    const int r0 = blockIdx.x * 128;
    const int b = r0 >> 10, hw0 = r0 & 1023;

    if (tid == 0) { nfull_s = 0; nref_s = 0; }
    __syncthreads();

    // classify
    if (tid < 128) {
        int row = r0 + tid;
        float V1 = FLT_MAX; int bi = 0x7fffffff;
        float v1[8], v2[8]; int i1[8];
        #pragma unroll
        for (int cb = 0; cb < NCB; cb++) {
            v1[cb] = g_pd[cb * N_ROWS + row];
            v2[cb] = g_ps[cb * N_ROWS + row];
            i1[cb] = g_pi[cb * N_ROWS + row];
            if (v1[cb] < V1 || (v1[cb] == V1 && i1[cb] < bi)) { V1 = v1[cb]; bi = i1[cb]; }
        }
        idx_sm[tid] = bi;
        float th = V1 + E2;
        bool unc = false; int nc = 0; int cl[8];
        #pragma unroll
        for (int cb = 0; cb < NCB; cb++) {
            if (v2[cb] < th) unc = true;
            if (v1[cb] < th) cl[nc++] = i1[cb];
        }
        if (unc) {
            full_list[atomicAdd(&nfull_s, 1)] = tid;
        } else if (nc > 1) {
            int p = atomicAdd(&nref_s, 1);
            ref_list[p] = tid;
            ccnt[tid] = nc;
            #pragma unroll
            for (int q = 0; q < 8; q++) if (q < nc) cand[tid][q] = cl[q];
        }
    }
    __syncthreads();

    // candidate refine: warp per entry, exact fp32
    for (int j = wid; j < nref_s; j += 8) {
        int rl = ref_list[j];
        int hw = hw0 + rl;
        float zreg[8];
        #pragma unroll
        for (int cc = 0; cc < 8; cc++)
            zreg[cc] = z_e[(((size_t)(b * C_DIM + cc * 32 + lane)) << 10) + hw];
        int nc = ccnt[rl];
        float bd = FLT_MAX; int bk = 0x7fffffff;
        for (int ci = 0; ci < nc; ci++) {
            int k = cand[rl][ci];
            const float* er = emb + (size_t)k * C_DIM;
            float acc = 0.0f;
            #pragma unroll
            for (int cc = 0; cc < 8; cc++)
                acc += zreg[cc] * er[cc * 32 + lane];
            #pragma unroll
            for (int m = 16; m; m >>= 1) acc += __shfl_xor_sync(0xffffffffu, acc, m);
            float dd = g_enorm[k] - 2.0f * acc;
            if (dd < bd || (dd == bd && k < bk)) { bd = dd; bk = k; }
        }
        if (lane == 0) idx_sm[rl] = bk;
    }

    // full-scan rescue: block-cooperative, coalesced via embT
    int nfull = nfull_s;
    for (int j = 0; j < nfull; j++) {
        int rl = full_list[j];
        __syncthreads();
        zrow[tid] = z_e[(((size_t)(b * C_DIM + tid)) << 10) + hw0 + rl];
        __syncthreads();
        float bd = FLT_MAX; int bk = 0x7fffffff;
        #pragma unroll
        for (int gch = 0; gch < 4; gch++) {
            int k = wid * 128 + gch * 32 + lane;
            float acc = 0.0f;
            #pragma unroll 8
            for (int c = 0; c < C_DIM; c++)
                acc = fmaf(zrow[c], embT[c * K_CODES + k], acc);
            float dd = g_enorm[k] + acc;
            if (dd < bd) { bd = dd; bk = k; }   // k increasing -> ties keep lower k
        }
        #pragma unroll
        for (int m = 16; m; m >>= 1) {
            float obd = __shfl_xor_sync(0xffffffffu, bd, m);
            int   obk = __shfl_xor_sync(0xffffffffu, bk, m);
            if (obd < bd || (obd == bd && obk < bk)) { bd = obd; bk = obk; }
        }
        if (lane == 0) { wd[wid] = bd; wk[wid] = bk; }
        __syncthreads();
        if (tid == 0) {
            float B = FLT_MAX; int K = 0x7fffffff;
            #pragma unroll
            for (int w = 0; w < 8; w++)
                if (wd[w] < B || (wd[w] == B && wk[w] < K)) { B = wd[w]; K = wk[w]; }
            idx_sm[rl] = K;
        }
    }
    __syncthreads();

    if (tid < 128) out_idx_f[r0 + tid] = (float)idx_sm[tid];

    // gather + loss partial
    for (int i = tid; i < 128 * 256; i += 256) {
        int r = i >> 8, c = i & 255;
        esm[r * 257 + c] = emb[idx_sm[r] * C_DIM + c];
    }
    __syncthreads();

    float acc = 0.0f;
    const int r = tid & 127, chalf = tid >> 7;
    for (int cc = 0; cc < 256; cc += 2) {
        int c = cc + chalf;
        float v = esm[r * 257 + c];
        size_t gi = (((size_t)(b * C_DIM + c)) << 10) + hw0 + r;
        float zv = z_e[gi];
        res[gi] = v;
        float df = v - zv;
        acc += df * df;
    }
    #pragma unroll
    for (int m = 16; m; m >>= 1) acc += __shfl_xor_sync(0xffffffffu, acc, m);
    if (lane == 0) wsum[wid] = acc;
    __syncthreads();
    if (tid == 0) {
        float s = 0.0f;
        #pragma unroll
        for (int w = 0; w < 8; w++) s += wsum[w];
        g_partial[blockIdx.x] = s;
    }
}

__global__ void k_loss(float* __restrict__ out_loss) {
    __shared__ float s[256];
    int tid = threadIdx.x;
    s[tid] = g_partial[tid];
    __syncthreads();
    for (int st = 128; st > 0; st >>= 1) {
        if (tid < st) s[tid] += s[tid + st];
        __syncthreads();
    }
    if (tid == 0) out_loss[0] = 1.25f * (s[0] / 8388608.0f);
}

// ---------------------------------------------------------------------------
extern "C" void kernel_launch(void* const* d_in, const int* in_sizes, int n_in,
                              void* d_out, int out_size)
{
    const float* z_e = (const float*)d_in[0];
    const float* emb = (const float*)d_in[1];

    float* out  = (float*)d_out;
    float* res  = out;
    float* loss = out + 8388608;
    float* idxf = out + 8388609;

    cudaFuncSetAttribute(k_mma,  cudaFuncAttributeMaxDynamicSharedMemorySize, SMEM_MMA);
    cudaFuncSetAttribute(k_post, cudaFuncAttributeMaxDynamicSharedMemorySize, SMEM_POST);

    k_prep <<<1152, 256>>>(z_e, emb);
    k_mma  <<<dim3(NCB, N_ROWS / 256), 256, SMEM_MMA>>>();
    k_post <<<N_ROWS / 128, 256, SMEM_POST>>>(z_e, emb, res, idxf);
    k_loss <<<1, 256>>>(loss);
}